// round 3
// baseline (speedup 1.0000x reference)
#include <cuda_runtime.h>
#include <cstdint>

#define DD 1024
#define VV 1024
#define BB 64
#define UU 512
#define TS 513           // U+1 steps
#define G3 3072
#define JJ 1024
#define NCTA 128         // persistent grid (<=148 SMs -> all co-resident)
#define KSPLIT 8

// ---------------- static device scratch (alloc-free rule) ----------------
__device__ __align__(16) float g_table[(size_t)VV * G3];        // W_ih@embed^T + b_ih  (12.6 MB)
__device__ __align__(16) float g_partial[(size_t)KSPLIT * BB * G3]; // k-split partials [ks][b][c]
__device__ __align__(16) float g_hs[(size_t)TS * BB * DD];      // all hidden states (134.5 MB)
__device__ __align__(16) float g_hbuf[2][BB * DD];              // ping-pong hidden state
__device__ unsigned g_bar_cnt;                                  // zero-init; restored each run
__device__ unsigned g_bar_phase;

// ---------------- software grid barrier (persistent kernel) ----------------
__device__ __forceinline__ void gsync(unsigned target) {
    __syncthreads();
    if (threadIdx.x == 0) {
        __threadfence();
        unsigned a = atomicAdd(&g_bar_cnt, 1u);
        if (a == (unsigned)gridDim.x - 1u) {
            *(volatile unsigned*)&g_bar_cnt = 0u;
            __threadfence();
            atomicExch(&g_bar_phase, target);
        } else {
            while (*(volatile unsigned*)&g_bar_phase != target) { }
            __threadfence();
        }
    }
    __syncthreads();
}

// ---------------- generic fp32 GEMM: C[m][n] = A[m][:].B[n][:] + bias[n] ----------------
// A:[M][1024] K-major, B:[N][1024] K-major. Tile 64x128, 256 thr, 4x8 micro-tile.
// remap=1: C-row = (m&63)*513 + (m>>6)   (hs[t,b] -> out[b,t])
__global__ __launch_bounds__(256, 1) void gemm_nt(
    const float* __restrict__ A, const float* __restrict__ Bm,
    const float* __restrict__ bias, float* __restrict__ C,
    int ldc, int remap)
{
    __shared__ float As[16][68];
    __shared__ float Bs[16][132];
    const int tid = threadIdx.x;
    const int m0 = blockIdx.y * 64;
    const int n0 = blockIdx.x * 128;
    const int tx = tid & 15;
    const int ty = tid >> 4;
    const int lr = tid >> 2;
    const int lq = tid & 3;

    float acc[4][8];
#pragma unroll
    for (int i = 0; i < 4; i++)
#pragma unroll
        for (int j = 0; j < 8; j++) acc[i][j] = 0.f;

#pragma unroll 1
    for (int k0 = 0; k0 < 1024; k0 += 16) {
        float4 av = *(const float4*)(A + (size_t)(m0 + lr) * 1024 + k0 + lq * 4);
        As[lq * 4 + 0][lr] = av.x; As[lq * 4 + 1][lr] = av.y;
        As[lq * 4 + 2][lr] = av.z; As[lq * 4 + 3][lr] = av.w;
#pragma unroll
        for (int p = 0; p < 2; p++) {
            int e = tid + p * 256;
            int rb = e >> 2, qb = e & 3;
            float4 bv = *(const float4*)(Bm + (size_t)(n0 + rb) * 1024 + k0 + qb * 4);
            Bs[qb * 4 + 0][rb] = bv.x; Bs[qb * 4 + 1][rb] = bv.y;
            Bs[qb * 4 + 2][rb] = bv.z; Bs[qb * 4 + 3][rb] = bv.w;
        }
        __syncthreads();
#pragma unroll
        for (int kk = 0; kk < 16; kk++) {
            float rm[4], rn[8];
#pragma unroll
            for (int i = 0; i < 4; i++) rm[i] = As[kk][ty + 16 * i];
#pragma unroll
            for (int j = 0; j < 8; j++) rn[j] = Bs[kk][tx + 16 * j];
#pragma unroll
            for (int i = 0; i < 4; i++)
#pragma unroll
                for (int j = 0; j < 8; j++) acc[i][j] += rm[i] * rn[j];
        }
        __syncthreads();
    }
#pragma unroll
    for (int i = 0; i < 4; i++) {
        int m = m0 + ty + 16 * i;
        int orow = remap ? ((m & 63) * TS + (m >> 6)) : m;
#pragma unroll
        for (int j = 0; j < 8; j++) {
            int n = n0 + tx + 16 * j;
            C[(size_t)orow * ldc + n] = acc[i][j] + bias[n];
        }
    }
}

// ---------------- persistent GRU recurrence ----------------
// Grid 128 CTAs x 256 thr. Per step:
//   Phase A: gh partials. CTA = (nt,ks): n-tile 192 cols of W_hh, k-slice 128.
//            Tile M=64(all b) x N=192, reg tile 8b x 6c per thread.
//   Phase B: reduce 8 partials, + table[tok] (gx incl. b_ih), gates, write h & hs.
__global__ __launch_bounds__(256, 1) void recurrent(
    const float* __restrict__ Whh, const float* __restrict__ bhh,
    const int* __restrict__ y, const float* __restrict__ h0)
{
    const int tid = threadIdx.x;
    const int lane = tid & 31;
    const int warp = tid >> 5;
    const int cta = blockIdx.x;
    const int nt = cta >> 3;     // 0..15 -> cols [nt*192, nt*192+192)
    const int ks = cta & 7;      // 0..7  -> k-range [ks*128, ks*128+128)

    __shared__ float h_s[16][68];
    __shared__ float w_s[16][196];

    unsigned target = *(volatile unsigned*)&g_bar_phase;  // safe: phase only moves after all arrive

    // broadcast initial_state into h buffer 0
    for (int e = cta * 256 + tid; e < BB * DD; e += NCTA * 256)
        g_hbuf[0][e] = h0[e & (DD - 1)];
    gsync(++target);

#pragma unroll 1
    for (int t = 0; t < TS; t++) {
        const float* __restrict__ hc = g_hbuf[t & 1];
        float* __restrict__ hn = g_hbuf[(t + 1) & 1];

        // ---- Phase A ----
        float acc[8][6];
#pragma unroll
        for (int i = 0; i < 8; i++)
#pragma unroll
            for (int j = 0; j < 6; j++) acc[i][j] = 0.f;

        const int kbase = ks * 128;
        const int lr = tid >> 2, lq = tid & 3;
#pragma unroll 1
        for (int kc = 0; kc < 128; kc += 16) {
            const int k0 = kbase + kc;
            // h chunk: [64 b][16 k] -> h_s[k][b]   (L2 read: L1 stale across barrier)
            float4 hv = __ldcg((const float4*)(hc + lr * DD + k0 + lq * 4));
            h_s[lq * 4 + 0][lr] = hv.x; h_s[lq * 4 + 1][lr] = hv.y;
            h_s[lq * 4 + 2][lr] = hv.z; h_s[lq * 4 + 3][lr] = hv.w;
            // W_hh chunk: [192 c][16 k] -> w_s[k][c]
#pragma unroll
            for (int p = 0; p < 3; p++) {
                int e = tid + p * 256;
                int r = e >> 2, q = e & 3;
                float4 wv = *(const float4*)(Whh + (size_t)(nt * 192 + r) * DD + k0 + q * 4);
                w_s[q * 4 + 0][r] = wv.x; w_s[q * 4 + 1][r] = wv.y;
                w_s[q * 4 + 2][r] = wv.z; w_s[q * 4 + 3][r] = wv.w;
            }
            __syncthreads();
#pragma unroll
            for (int kk = 0; kk < 16; kk++) {
                float4 ha = *(const float4*)&h_s[kk][warp * 8];
                float4 hb = *(const float4*)&h_s[kk][warp * 8 + 4];
                float rh[8] = {ha.x, ha.y, ha.z, ha.w, hb.x, hb.y, hb.z, hb.w};
                float rw[6];
#pragma unroll
                for (int j = 0; j < 6; j++) rw[j] = w_s[kk][lane + 32 * j];
#pragma unroll
                for (int i = 0; i < 8; i++)
#pragma unroll
                    for (int j = 0; j < 6; j++) acc[i][j] += rh[i] * rw[j];
            }
            __syncthreads();
        }
        // partials [ks][b][c] (lane-contiguous c -> coalesced)
#pragma unroll
        for (int j = 0; j < 6; j++) {
            const int c = nt * 192 + lane + 32 * j;
#pragma unroll
            for (int i = 0; i < 8; i++)
                g_partial[((size_t)ks * BB + warp * 8 + i) * G3 + c] = acc[i][j];
        }
        gsync(++target);

        // ---- Phase B: gates ----
        for (int e = cta * 256 + tid; e < BB * DD; e += NCTA * 256) {
            const int b = e >> 10;
            const int j = e & (DD - 1);
            const int tok = (t == 0) ? 0 : y[b * UU + (t - 1)];
            float ghr = bhh[j], ghz = bhh[DD + j], ghn = bhh[2 * DD + j];
#pragma unroll
            for (int s = 0; s < KSPLIT; s++) {
                const float* pp = g_partial + ((size_t)s * BB + b) * G3;
                ghr += __ldcg(pp + j);
                ghz += __ldcg(pp + DD + j);
                ghn += __ldcg(pp + 2 * DD + j);
            }
            const float* tb = g_table + (size_t)tok * G3;
            float xr = tb[j] + ghr;
            float xz = tb[DD + j] + ghz;
            float xn = tb[2 * DD + j];
            float rg = 1.f / (1.f + __expf(-xr));
            float zg = 1.f / (1.f + __expf(-xz));
            float ng = tanhf(xn + rg * ghn);
            float hv = (1.f - zg) * ng + zg * __ldcg(hc + e);
            hn[e] = hv;
            g_hs[((size_t)t * BB + b) * DD + j] = hv;
        }
        gsync(++target);
    }
}

// ---------------- launch ----------------
extern "C" void kernel_launch(void* const* d_in, const int* in_sizes, int n_in,
                              void* d_out, int out_size) {
    const int*   y     = (const int*)d_in[0];
    const float* embed = (const float*)d_in[1];
    const float* wih   = (const float*)d_in[2];
    const float* bih   = (const float*)d_in[3];
    const float* whh   = (const float*)d_in[4];
    const float* bhh   = (const float*)d_in[5];
    const float* lw    = (const float*)d_in[6];
    const float* lb    = (const float*)d_in[7];
    const float* h0    = (const float*)d_in[8];
    float* out = (float*)d_out;

    float *tbl = nullptr, *hs = nullptr;
    cudaGetSymbolAddress((void**)&tbl, g_table);
    cudaGetSymbolAddress((void**)&hs, g_hs);

    // 1) vocab table: table[v][0:3072] = embed[v]·W_ih^T + b_ih
    gemm_nt<<<dim3(G3 / 128, VV / 64), 256>>>(embed, wih, bih, tbl, G3, 0);
    // 2) persistent recurrence over 513 steps
    recurrent<<<NCTA, 256>>>(whh, bhh, y, h0);
    // 3) out[b][t][:] = hs[t*64+b]·linear_w^T + linear_b   (row remap in epilogue)
    gemm_nt<<<dim3(JJ / 128, (TS * BB) / 64), 256>>>(hs, lw, lb, out, JJ, 1);
}

// round 6
// speedup vs baseline: 1.0024x; 1.0024x over previous
#include <cuda_runtime.h>
#include <cstdint>

#define DD 1024
#define VV 1024
#define BB 64
#define UU 512
#define TS 513           // U+1 steps
#define G3 3072
#define JJ 1024
#define NCTA 128         // persistent grid (<=148 SMs -> all co-resident)
#define KSPLIT 8

// ---------------- f32x2 packed-FMA helpers ----------------
__device__ __forceinline__ unsigned long long pack2(float x, float y) {
    unsigned long long r;
    asm("mov.b64 %0, {%1, %2};" : "=l"(r) : "f"(x), "f"(y));
    return r;
}
__device__ __forceinline__ unsigned long long fma2(unsigned long long a,
                                                   unsigned long long b,
                                                   unsigned long long c) {
    unsigned long long d;
    asm("fma.rn.f32x2 %0, %1, %2, %3;" : "=l"(d) : "l"(a), "l"(b), "l"(c));
    return d;
}
__device__ __forceinline__ float2 unpack2(unsigned long long v) {
    float2 f;
    asm("mov.b64 {%0, %1}, %2;" : "=f"(f.x), "=f"(f.y) : "l"(v));
    return f;
}

// ---------------- static device scratch (alloc-free rule) ----------------
__device__ __align__(16) float g_table[(size_t)VV * G3];            // W_ih@embed^T + b_ih
__device__ __align__(16) float g_partial[(size_t)KSPLIT * BB * G3]; // k-split partials [ks][b][c]
__device__ __align__(16) float g_hs[(size_t)TS * BB * DD];          // all hidden states
__device__ __align__(16) float g_hbuf[2][BB * DD];                  // ping-pong hidden state
__device__ unsigned g_bar_cnt;
__device__ unsigned g_bar_phase;

// ---------------- software grid barrier (persistent kernel) ----------------
__device__ __forceinline__ void gsync(unsigned target) {
    __syncthreads();
    if (threadIdx.x == 0) {
        __threadfence();
        unsigned a = atomicAdd(&g_bar_cnt, 1u);
        if (a == (unsigned)gridDim.x - 1u) {
            *(volatile unsigned*)&g_bar_cnt = 0u;
            __threadfence();
            atomicExch(&g_bar_phase, target);
        } else {
            while (*(volatile unsigned*)&g_bar_phase != target) { }
            __threadfence();
        }
    }
    __syncthreads();
}

// ---------------- fp32 GEMM v2: C[m][n] = A[m][:].B[n][:] + bias[n] ----------------
// A:[M][1024] K-major, B:[N][1024] K-major. Tile 128x128, 256 thr, 8x8 micro-tile,
// f32x2 packed along n. remap=1: C-row = (m&63)*TS + (m>>6).
__global__ __launch_bounds__(256, 1) void gemm_nt(
    const float* __restrict__ A, const float* __restrict__ Bm,
    const float* __restrict__ bias, float* __restrict__ C,
    int M, int ldc, int remap)
{
    __shared__ float As[16][132];
    __shared__ float Bs[16][132];
    const int tid = threadIdx.x;
    const int m0 = blockIdx.y * 128;
    const int n0 = blockIdx.x * 128;
    const int tn = tid & 15;     // n-group: n-local = tn*8
    const int tm = tid >> 4;     // m-group: m-local = tm*8

    unsigned long long acc2[8][4];
#pragma unroll
    for (int i = 0; i < 8; i++)
#pragma unroll
        for (int j = 0; j < 4; j++) acc2[i][j] = 0ull;

#pragma unroll 1
    for (int k0 = 0; k0 < 1024; k0 += 16) {
        // cooperative load: 128 rows x 16 k for both A and B
#pragma unroll
        for (int p = 0; p < 2; p++) {
            int e = tid + p * 256;
            int r = e >> 2, q = e & 3;
            int arow = m0 + r; if (arow >= M) arow = M - 1;   // clamp (out-gemm tail)
            float4 av = *(const float4*)(A + (size_t)arow * 1024 + k0 + q * 4);
            As[q * 4 + 0][r] = av.x; As[q * 4 + 1][r] = av.y;
            As[q * 4 + 2][r] = av.z; As[q * 4 + 3][r] = av.w;
            float4 bv = *(const float4*)(Bm + (size_t)(n0 + r) * 1024 + k0 + q * 4);
            Bs[q * 4 + 0][r] = bv.x; Bs[q * 4 + 1][r] = bv.y;
            Bs[q * 4 + 2][r] = bv.z; Bs[q * 4 + 3][r] = bv.w;
        }
        __syncthreads();
#pragma unroll
        for (int kk = 0; kk < 16; kk++) {
            unsigned long long rn2[4];
#pragma unroll
            for (int j = 0; j < 4; j++)
                rn2[j] = *(const unsigned long long*)&Bs[kk][tn * 8 + 2 * j];
            float4 a0 = *(const float4*)&As[kk][tm * 8];
            float4 a1 = *(const float4*)&As[kk][tm * 8 + 4];
            float rm[8] = {a0.x, a0.y, a0.z, a0.w, a1.x, a1.y, a1.z, a1.w};
#pragma unroll
            for (int i = 0; i < 8; i++) {
                unsigned long long rm2 = pack2(rm[i], rm[i]);
#pragma unroll
                for (int j = 0; j < 4; j++)
                    acc2[i][j] = fma2(rm2, rn2[j], acc2[i][j]);
            }
        }
        __syncthreads();
    }

    float b8[8];
#pragma unroll
    for (int u = 0; u < 8; u++) b8[u] = bias[n0 + tn * 8 + u];

#pragma unroll
    for (int i = 0; i < 8; i++) {
        int m = m0 + tm * 8 + i;
        if (m >= M) break;
        int orow = remap ? ((m & 63) * TS + (m >> 6)) : m;
        float2 v0 = unpack2(acc2[i][0]);
        float2 v1 = unpack2(acc2[i][1]);
        float2 v2 = unpack2(acc2[i][2]);
        float2 v3 = unpack2(acc2[i][3]);
        float4 o0 = {v0.x + b8[0], v0.y + b8[1], v1.x + b8[2], v1.y + b8[3]};
        float4 o1 = {v2.x + b8[4], v2.y + b8[5], v3.x + b8[6], v3.y + b8[7]};
        *(float4*)(C + (size_t)orow * ldc + n0 + tn * 8) = o0;
        *(float4*)(C + (size_t)orow * ldc + n0 + tn * 8 + 4) = o1;
    }
}

// ---------------- persistent GRU recurrence ----------------
// Grid 128 CTAs x 256 thr. Per step:
//   Phase A: gh partials. CTA = (nt,ks): n-tile 192 cols of W_hh, k-slice 128.
//            Tile M=64(batch) x N=192; thread tile 8b x 6c, f32x2 packed over batch.
//   Phase B: reduce 8 partials, + table[tok] (gx incl. b_ih), gates, write h & hs.
__global__ __launch_bounds__(256, 1) void recurrent(
    const float* __restrict__ Whh, const float* __restrict__ bhh,
    const int* __restrict__ y, const float* __restrict__ h0)
{
    const int tid = threadIdx.x;
    const int lane = tid & 31;
    const int warp = tid >> 5;
    const int cta = blockIdx.x;
    const int nt = cta >> 3;     // 0..15 -> cols [nt*192, nt*192+192)
    const int ks = cta & 7;      // 0..7  -> k-range [ks*128, ks*128+128)

    __shared__ float h_s[16][68];
    __shared__ float w_s[16][196];

    unsigned target = *(volatile unsigned*)&g_bar_phase;

    for (int e = cta * 256 + tid; e < BB * DD; e += NCTA * 256)
        g_hbuf[0][e] = h0[e & (DD - 1)];
    gsync(++target);

#pragma unroll 1
    for (int t = 0; t < TS; t++) {
        const float* __restrict__ hc = g_hbuf[t & 1];
        float* __restrict__ hn = g_hbuf[(t + 1) & 1];

        // ---- Phase A ----
        unsigned long long acc2[4][6];
#pragma unroll
        for (int i = 0; i < 4; i++)
#pragma unroll
            for (int j = 0; j < 6; j++) acc2[i][j] = 0ull;

        const int kbase = ks * 128;
        const int lr = tid >> 2, lq = tid & 3;
#pragma unroll 1
        for (int kc = 0; kc < 128; kc += 16) {
            const int k0 = kbase + kc;
            // h chunk: [64 b][16 k] -> h_s[k][b]  (L2 read: L1 stale across barrier)
            float4 hv = __ldcg((const float4*)(hc + lr * DD + k0 + lq * 4));
            h_s[lq * 4 + 0][lr] = hv.x; h_s[lq * 4 + 1][lr] = hv.y;
            h_s[lq * 4 + 2][lr] = hv.z; h_s[lq * 4 + 3][lr] = hv.w;
            // W_hh chunk: [192 c][16 k] -> w_s[k][c]
#pragma unroll
            for (int p = 0; p < 3; p++) {
                int e = tid + p * 256;
                int r = e >> 2, q = e & 3;
                float4 wv = *(const float4*)(Whh + (size_t)(nt * 192 + r) * DD + k0 + q * 4);
                w_s[q * 4 + 0][r] = wv.x; w_s[q * 4 + 1][r] = wv.y;
                w_s[q * 4 + 2][r] = wv.z; w_s[q * 4 + 3][r] = wv.w;
            }
            __syncthreads();
#pragma unroll
            for (int kk = 0; kk < 16; kk++) {
                unsigned long long rh2[4];
#pragma unroll
                for (int i = 0; i < 4; i++)
                    rh2[i] = *(const unsigned long long*)&h_s[kk][warp * 8 + 2 * i];
#pragma unroll
                for (int j = 0; j < 6; j++) {
                    float w = w_s[kk][lane + 32 * j];
                    unsigned long long rw2 = pack2(w, w);
#pragma unroll
                    for (int i = 0; i < 4; i++)
                        acc2[i][j] = fma2(rh2[i], rw2, acc2[i][j]);
                }
            }
            __syncthreads();
        }
        // partials [ks][b][c] (lane-contiguous c -> coalesced)
#pragma unroll
        for (int j = 0; j < 6; j++) {
            const int c = nt * 192 + lane + 32 * j;
#pragma unroll
            for (int i = 0; i < 4; i++) {
                float2 v = unpack2(acc2[i][j]);
                const int b = warp * 8 + 2 * i;
                g_partial[((size_t)ks * BB + b) * G3 + c] = v.x;
                g_partial[((size_t)ks * BB + b + 1) * G3 + c] = v.y;
            }
        }
        gsync(++target);

        // ---- Phase B: gates ----
        for (int e = cta * 256 + tid; e < BB * DD; e += NCTA * 256) {
            const int b = e >> 10;
            const int j = e & (DD - 1);
            const int tok = (t == 0) ? 0 : y[b * UU + (t - 1)];
            float ghr = bhh[j], ghz = bhh[DD + j], ghn = bhh[2 * DD + j];
#pragma unroll
            for (int s = 0; s < KSPLIT; s++) {
                const float* pp = g_partial + ((size_t)s * BB + b) * G3;
                ghr += __ldcg(pp + j);
                ghz += __ldcg(pp + DD + j);
                ghn += __ldcg(pp + 2 * DD + j);
            }
            const float* tb = g_table + (size_t)tok * G3;
            float xr = tb[j] + ghr;
            float xz = tb[DD + j] + ghz;
            float xn = tb[2 * DD + j];
            float rg = 1.f / (1.f + __expf(-xr));
            float zg = 1.f / (1.f + __expf(-xz));
            float ng = tanhf(xn + rg * ghn);
            float hv = (1.f - zg) * ng + zg * __ldcg(hc + e);
            hn[e] = hv;
            g_hs[((size_t)t * BB + b) * DD + j] = hv;
        }
        gsync(++target);
    }
}

// ---------------- launch ----------------
extern "C" void kernel_launch(void* const* d_in, const int* in_sizes, int n_in,
                              void* d_out, int out_size) {
    const int*   y     = (const int*)d_in[0];
    const float* embed = (const float*)d_in[1];
    const float* wih   = (const float*)d_in[2];
    const float* bih   = (const float*)d_in[3];
    const float* whh   = (const float*)d_in[4];
    const float* bhh   = (const float*)d_in[5];
    const float* lw    = (const float*)d_in[6];
    const float* lb    = (const float*)d_in[7];
    const float* h0    = (const float*)d_in[8];
    float* out = (float*)d_out;

    float *tbl = nullptr, *hs = nullptr;
    cudaGetSymbolAddress((void**)&tbl, g_table);
    cudaGetSymbolAddress((void**)&hs, g_hs);

    // 1) vocab table: table[v][0:3072] = embed[v]·W_ih^T + b_ih
    gemm_nt<<<dim3(G3 / 128, VV / 128), 256>>>(embed, wih, bih, tbl, VV, G3, 0);
    // 2) persistent recurrence over 513 steps
    recurrent<<<NCTA, 256>>>(whh, bhh, y, h0);
    // 3) out[b][t][:] = hs[t*64+b]·linear_w^T + linear_b  (row remap in epilogue)
    gemm_nt<<<dim3(JJ / 128, (TS * BB + 127) / 128), 256>>>(hs, lw, lb, out, TS * BB, JJ, 1);
}

// round 8
// speedup vs baseline: 1.1433x; 1.1406x over previous
#include <cuda_runtime.h>
#include <cstdint>

#define DD 1024
#define VV 1024
#define BB 64
#define UU 512
#define TS 513           // U+1 steps
#define G3 3072
#define JJ 1024
#define NCTA 128         // persistent grid: nt(16) x ks(8)
#define KSPLIT 8

// ---------------- f32x2 packed-FMA helpers ----------------
__device__ __forceinline__ unsigned long long pack2(float x, float y) {
    unsigned long long r;
    asm("mov.b64 %0, {%1, %2};" : "=l"(r) : "f"(x), "f"(y));
    return r;
}
__device__ __forceinline__ unsigned long long fma2(unsigned long long a,
                                                   unsigned long long b,
                                                   unsigned long long c) {
    unsigned long long d;
    asm("fma.rn.f32x2 %0, %1, %2, %3;" : "=l"(d) : "l"(a), "l"(b), "l"(c));
    return d;
}
__device__ __forceinline__ float2 unpack2(unsigned long long v) {
    float2 f;
    asm("mov.b64 {%0, %1}, %2;" : "=f"(f.x), "=f"(f.y) : "l"(v));
    return f;
}

// ---------------- static device scratch (alloc-free rule) ----------------
__device__ __align__(16) float g_table[(size_t)VV * G3];            // W_ih@embed^T + b_ih
__device__ __align__(16) float g_partial[(size_t)KSPLIT * BB * G3]; // k-split partials [ks][b][c]
__device__ __align__(16) float g_hs[(size_t)TS * BB * DD];          // all hidden states
__device__ __align__(16) float g_hbuf[2][BB * DD];                  // ping-pong hidden state
__device__ unsigned g_bar_cnt;
__device__ unsigned g_bar_phase;

// ---------------- software grid barrier (persistent kernel) ----------------
__device__ __forceinline__ void gsync(unsigned target) {
    __syncthreads();
    if (threadIdx.x == 0) {
        __threadfence();
        unsigned a = atomicAdd(&g_bar_cnt, 1u);
        if (a == (unsigned)gridDim.x - 1u) {
            *(volatile unsigned*)&g_bar_cnt = 0u;
            __threadfence();
            atomicExch(&g_bar_phase, target);
        } else {
            while (*(volatile unsigned*)&g_bar_phase != target) { }
            __threadfence();
        }
    }
    __syncthreads();
}

// ---------------- fp32 GEMM v3: C[m][n] = A[m][:].B[n][:] + bias[n] ----------------
// A:[M][1024] K-major, B:[N][1024] K-major. Tile 64x128, 256 thr.
// Thread (tx,ty): tx=tid&15 owns n-pairs {2tx+32j}, ty=tid>>4 owns m rows {ty+16i}.
// f32x2 packed over adjacent n (lane-stride-2 LDS.64: conflict-free).
// M must be a multiple of 64. remap=1: C-row = (m&63)*TS + (m>>6).
__global__ __launch_bounds__(256, 2) void gemm_nt(
    const float* __restrict__ A, const float* __restrict__ Bm,
    const float* __restrict__ bias, float* __restrict__ C,
    int ldc, int remap)
{
    __shared__ float As[16][68];
    __shared__ float Bs[16][132];
    const int tid = threadIdx.x;
    const int m0 = blockIdx.y * 64;
    const int n0 = blockIdx.x * 128;
    const int tx = tid & 15;
    const int ty = tid >> 4;
    const int ar = tid >> 2, aq = tid & 3;

    unsigned long long acc2[4][4];
#pragma unroll
    for (int i = 0; i < 4; i++)
#pragma unroll
        for (int j = 0; j < 4; j++) acc2[i][j] = 0ull;

#pragma unroll 1
    for (int k0 = 0; k0 < 1024; k0 += 16) {
        // A: 64 rows x 16 k (1 float4/thread)
        float4 av = *(const float4*)(A + (size_t)(m0 + ar) * 1024 + k0 + aq * 4);
        As[aq * 4 + 0][ar] = av.x; As[aq * 4 + 1][ar] = av.y;
        As[aq * 4 + 2][ar] = av.z; As[aq * 4 + 3][ar] = av.w;
        // B: 128 rows x 16 k (2 float4/thread)
#pragma unroll
        for (int p = 0; p < 2; p++) {
            int e = tid + p * 256;
            int r = e >> 2, q = e & 3;
            float4 bv = *(const float4*)(Bm + (size_t)(n0 + r) * 1024 + k0 + q * 4);
            Bs[q * 4 + 0][r] = bv.x; Bs[q * 4 + 1][r] = bv.y;
            Bs[q * 4 + 2][r] = bv.z; Bs[q * 4 + 3][r] = bv.w;
        }
        __syncthreads();
#pragma unroll
        for (int kk = 0; kk < 16; kk++) {
            unsigned long long rn2[4];
#pragma unroll
            for (int j = 0; j < 4; j++)
                rn2[j] = *(const unsigned long long*)&Bs[kk][tx * 2 + 32 * j];
#pragma unroll
            for (int i = 0; i < 4; i++) {
                float a = As[kk][ty + 16 * i];
                unsigned long long am = pack2(a, a);
#pragma unroll
                for (int j = 0; j < 4; j++)
                    acc2[i][j] = fma2(am, rn2[j], acc2[i][j]);
            }
        }
        __syncthreads();
    }

    float2 b2[4];
#pragma unroll
    for (int j = 0; j < 4; j++)
        b2[j] = *(const float2*)(bias + n0 + tx * 2 + 32 * j);

#pragma unroll
    for (int i = 0; i < 4; i++) {
        int m = m0 + ty + 16 * i;
        int orow = remap ? ((m & 63) * TS + (m >> 6)) : m;
#pragma unroll
        for (int j = 0; j < 4; j++) {
            float2 v = unpack2(acc2[i][j]);
            float2 o = {v.x + b2[j].x, v.y + b2[j].y};
            *(float2*)(C + (size_t)orow * ldc + n0 + tx * 2 + 32 * j) = o;
        }
    }
}

// ---------------- persistent GRU recurrence v2 ----------------
// Grid 128 CTAs x 256 thr. CTA = (nt,ks): 192 cols x 128-k slice of W_hh,
// held ENTIRELY in shared memory for all 513 steps (96KB). h chunks are
// double-buffered with register prefetch. Phase B unchanged.
#define WSL (192 * 128)          // W slice floats
#define HBUF (16 * 68)           // one h chunk buffer [16 k][68 b-pad]
__global__ __launch_bounds__(256, 1) void recurrent(
    const float* __restrict__ Whh, const float* __restrict__ bhh,
    const int* __restrict__ y, const float* __restrict__ h0)
{
    extern __shared__ float smem[];
    float* w_s = smem;                 // [128 k][192 c], stride 192
    float* h_s = smem + WSL;           // [2][16][68]

    const int tid = threadIdx.x;
    const int lane = tid & 31;
    const int warp = tid >> 5;
    const int cta = blockIdx.x;
    const int nt = cta >> 3;     // 0..15 -> cols [nt*192, +192)
    const int ks = cta & 7;      // 0..7  -> k-range [ks*128, +128)
    const int kbase = ks * 128;
    const int lr = tid >> 2, lq = tid & 3;

    unsigned target = *(volatile unsigned*)&g_bar_phase;

    // ---- load W slice into smem ONCE (192 rows x 128 k = 6144 float4) ----
#pragma unroll 4
    for (int p = 0; p < 24; p++) {
        int e = tid + p * 256;
        int r = e >> 5;              // 0..191 (col)
        int q = e & 31;              // 0..31  (k-float4)
        float4 wv = *(const float4*)(Whh + (size_t)(nt * 192 + r) * DD + kbase + q * 4);
        w_s[(q * 4 + 0) * 192 + r] = wv.x;
        w_s[(q * 4 + 1) * 192 + r] = wv.y;
        w_s[(q * 4 + 2) * 192 + r] = wv.z;
        w_s[(q * 4 + 3) * 192 + r] = wv.w;
    }

    // broadcast initial_state into h buffer 0
    for (int e = cta * 256 + tid; e < BB * DD; e += NCTA * 256)
        g_hbuf[0][e] = h0[e & (DD - 1)];
    gsync(++target);

#pragma unroll 1
    for (int t = 0; t < TS; t++) {
        const float* __restrict__ hc = g_hbuf[t & 1];
        float* __restrict__ hn = g_hbuf[(t + 1) & 1];

        // ---- Phase A: gh partial (64 b x 192 c, K=128) ----
        unsigned long long acc2[4][6];
#pragma unroll
        for (int i = 0; i < 4; i++)
#pragma unroll
            for (int j = 0; j < 6; j++) acc2[i][j] = 0ull;

        // preload chunk 0 of h
        {
            float4 hv = __ldcg((const float4*)(hc + lr * DD + kbase + lq * 4));
            float* hb = h_s;
            hb[(lq * 4 + 0) * 68 + lr] = hv.x; hb[(lq * 4 + 1) * 68 + lr] = hv.y;
            hb[(lq * 4 + 2) * 68 + lr] = hv.z; hb[(lq * 4 + 3) * 68 + lr] = hv.w;
        }
        __syncthreads();

#pragma unroll 1
        for (int c = 0; c < 8; c++) {
            float4 pf;
            if (c < 7)
                pf = __ldcg((const float4*)(hc + lr * DD + kbase + (c + 1) * 16 + lq * 4));
            const float* hb = h_s + (c & 1) * HBUF;
            const float* wb = w_s + c * 16 * 192;
#pragma unroll
            for (int kk = 0; kk < 16; kk++) {
                unsigned long long rh2[4];
#pragma unroll
                for (int i = 0; i < 4; i++)
                    rh2[i] = *(const unsigned long long*)&hb[kk * 68 + warp * 8 + 2 * i];
#pragma unroll
                for (int j = 0; j < 6; j++) {
                    float w = wb[kk * 192 + lane + 32 * j];
                    unsigned long long rw2 = pack2(w, w);
#pragma unroll
                    for (int i = 0; i < 4; i++)
                        acc2[i][j] = fma2(rh2[i], rw2, acc2[i][j]);
                }
            }
            if (c < 7) {
                float* hb2 = h_s + ((c + 1) & 1) * HBUF;
                hb2[(lq * 4 + 0) * 68 + lr] = pf.x; hb2[(lq * 4 + 1) * 68 + lr] = pf.y;
                hb2[(lq * 4 + 2) * 68 + lr] = pf.z; hb2[(lq * 4 + 3) * 68 + lr] = pf.w;
                __syncthreads();
            }
        }
        // partials [ks][b][c] (lane-contiguous c -> coalesced)
#pragma unroll
        for (int j = 0; j < 6; j++) {
            const int col = nt * 192 + lane + 32 * j;
#pragma unroll
            for (int i = 0; i < 4; i++) {
                float2 v = unpack2(acc2[i][j]);
                const int b = warp * 8 + 2 * i;
                g_partial[((size_t)ks * BB + b) * G3 + col] = v.x;
                g_partial[((size_t)ks * BB + b + 1) * G3 + col] = v.y;
            }
        }
        gsync(++target);

        // ---- Phase B: gates ----
        for (int e = cta * 256 + tid; e < BB * DD; e += NCTA * 256) {
            const int b = e >> 10;
            const int j = e & (DD - 1);
            const int tok = (t == 0) ? 0 : y[b * UU + (t - 1)];
            float ghr = bhh[j], ghz = bhh[DD + j], ghn = bhh[2 * DD + j];
#pragma unroll
            for (int s = 0; s < KSPLIT; s++) {
                const float* pp = g_partial + ((size_t)s * BB + b) * G3;
                ghr += __ldcg(pp + j);
                ghz += __ldcg(pp + DD + j);
                ghn += __ldcg(pp + 2 * DD + j);
            }
            const float* tb = g_table + (size_t)tok * G3;
            float xr = tb[j] + ghr;
            float xz = tb[DD + j] + ghz;
            float xn = tb[2 * DD + j];
            float rg = 1.f / (1.f + __expf(-xr));
            float zg = 1.f / (1.f + __expf(-xz));
            float ng = tanhf(xn + rg * ghn);
            float hv = (1.f - zg) * ng + zg * __ldcg(hc + e);
            hn[e] = hv;
            g_hs[((size_t)t * BB + b) * DD + j] = hv;
        }
        gsync(++target);
    }
}

// ---------------- launch ----------------
extern "C" void kernel_launch(void* const* d_in, const int* in_sizes, int n_in,
                              void* d_out, int out_size) {
    const int*   y     = (const int*)d_in[0];
    const float* embed = (const float*)d_in[1];
    const float* wih   = (const float*)d_in[2];
    const float* bih   = (const float*)d_in[3];
    const float* whh   = (const float*)d_in[4];
    const float* bhh   = (const float*)d_in[5];
    const float* lw    = (const float*)d_in[6];
    const float* lb    = (const float*)d_in[7];
    const float* h0    = (const float*)d_in[8];
    float* out = (float*)d_out;

    float *tbl = nullptr, *hs = nullptr;
    cudaGetSymbolAddress((void**)&tbl, g_table);
    cudaGetSymbolAddress((void**)&hs, g_hs);

    const int rec_smem = (WSL + 2 * HBUF) * sizeof(float);  // 96KB + 8.5KB
    static bool attr_done = false;
    if (!attr_done) {
        cudaFuncSetAttribute(recurrent, cudaFuncAttributeMaxDynamicSharedMemorySize, rec_smem);
        attr_done = true;
    }

    // 1) vocab table: table[v][0:3072] = embed[v]·W_ih^T + b_ih
    gemm_nt<<<dim3(G3 / 128, VV / 64), 256>>>(embed, wih, bih, tbl, G3, 0);
    // 2) persistent recurrence over 513 steps
    recurrent<<<NCTA, 256, rec_smem>>>(whh, bhh, y, h0);
    // 3) out[b][t][:] = hs[t*64+b]·linear_w^T + linear_b  (row remap in epilogue)
    gemm_nt<<<dim3(JJ / 128, (TS * BB) / 64), 256>>>(hs, lw, lb, out, JJ, 1);
}

// round 10
// speedup vs baseline: 1.2096x; 1.0579x over previous
#include <cuda_runtime.h>
#include <cstdint>

#define DD 1024
#define VV 1024
#define BB 64
#define UU 512
#define TS 513           // U+1 steps
#define G3 3072
#define JJ 1024
#define NCTA 128         // 128 CTAs x 8 j-cols each = 1024 gate-triples

// recurrent smem layout (floats)
#define WS_FLOATS (1024 * 24)            // W slice [k][24 rows]
#define HB_STRIDE 66                     // h chunk row stride (conflict-free)
#define HB_FLOATS (128 * HB_STRIDE)      // one h chunk [128 k][66]
#define H_OFF WS_FLOATS
#define Y_OFF (WS_FLOATS + 2 * HB_FLOATS)
#define SM_FLOATS (Y_OFF + 64)

// ---------------- f32x2 packed-FMA helpers ----------------
__device__ __forceinline__ unsigned long long pack2(float x, float y) {
    unsigned long long r;
    asm("mov.b64 %0, {%1, %2};" : "=l"(r) : "f"(x), "f"(y));
    return r;
}
__device__ __forceinline__ unsigned long long fma2(unsigned long long a,
                                                   unsigned long long b,
                                                   unsigned long long c) {
    unsigned long long d;
    asm("fma.rn.f32x2 %0, %1, %2, %3;" : "=l"(d) : "l"(a), "l"(b), "l"(c));
    return d;
}
__device__ __forceinline__ float2 unpack2(unsigned long long v) {
    float2 f;
    asm("mov.b64 {%0, %1}, %2;" : "=f"(f.x), "=f"(f.y) : "l"(v));
    return f;
}

// ---------------- static device scratch (alloc-free rule) ----------------
__device__ __align__(16) float g_table[(size_t)VV * G3];   // W_ih@embed^T + b_ih
__device__ __align__(16) float g_hs[(size_t)TS * BB * DD]; // all hidden states
__device__ __align__(16) float g_hbuf[2][BB * DD];         // ping-pong hidden state
__device__ unsigned g_bar_cnt;
__device__ unsigned g_bar_phase;

// ---------------- software grid barrier ----------------
__device__ __forceinline__ void gsync(unsigned target) {
    __syncthreads();
    if (threadIdx.x == 0) {
        __threadfence();
        unsigned a = atomicAdd(&g_bar_cnt, 1u);
        if (a == (unsigned)gridDim.x - 1u) {
            *(volatile unsigned*)&g_bar_cnt = 0u;
            __threadfence();
            atomicExch(&g_bar_phase, target);
        } else {
            while (*(volatile unsigned*)&g_bar_phase != target) { }
            __threadfence();
        }
    }
    __syncthreads();
}

// ---------------- fp32 GEMM v4 (double-buffered): C = A.B^T + bias ----------------
// A:[M][1024] K-major, B:[N][1024] K-major. Tile 64x128, 256 thr, f32x2 over n.
// M multiple of 64. remap=1: C-row = (m&63)*TS + (m>>6).
__global__ __launch_bounds__(256, 2) void gemm_nt(
    const float* __restrict__ A, const float* __restrict__ Bm,
    const float* __restrict__ bias, float* __restrict__ C,
    int ldc, int remap)
{
    __shared__ float As[2][16][68];
    __shared__ float Bs[2][16][132];
    const int tid = threadIdx.x;
    const int m0 = blockIdx.y * 64;
    const int n0 = blockIdx.x * 128;
    const int tx = tid & 15;
    const int ty = tid >> 4;
    const int ar = tid >> 2, aq = tid & 3;
    const int br0 = (tid) >> 2, bq0 = tid & 3;
    const int br1 = (tid + 256) >> 2, bq1 = tid & 3;

    unsigned long long acc2[4][4];
#pragma unroll
    for (int i = 0; i < 4; i++)
#pragma unroll
        for (int j = 0; j < 4; j++) acc2[i][j] = 0ull;

    // preload stage 0
    {
        float4 av = *(const float4*)(A + (size_t)(m0 + ar) * 1024 + aq * 4);
        As[0][aq * 4 + 0][ar] = av.x; As[0][aq * 4 + 1][ar] = av.y;
        As[0][aq * 4 + 2][ar] = av.z; As[0][aq * 4 + 3][ar] = av.w;
        float4 b0 = *(const float4*)(Bm + (size_t)(n0 + br0) * 1024 + bq0 * 4);
        Bs[0][bq0 * 4 + 0][br0] = b0.x; Bs[0][bq0 * 4 + 1][br0] = b0.y;
        Bs[0][bq0 * 4 + 2][br0] = b0.z; Bs[0][bq0 * 4 + 3][br0] = b0.w;
        float4 b1 = *(const float4*)(Bm + (size_t)(n0 + br1) * 1024 + bq1 * 4);
        Bs[0][bq1 * 4 + 0][br1] = b1.x; Bs[0][bq1 * 4 + 1][br1] = b1.y;
        Bs[0][bq1 * 4 + 2][br1] = b1.z; Bs[0][bq1 * 4 + 3][br1] = b1.w;
    }
    __syncthreads();

#pragma unroll 1
    for (int it = 0; it < 64; it++) {
        const int cur = it & 1;
        float4 avN, b0N, b1N;
        if (it < 63) {
            const int k0 = (it + 1) * 16;
            avN = *(const float4*)(A + (size_t)(m0 + ar) * 1024 + k0 + aq * 4);
            b0N = *(const float4*)(Bm + (size_t)(n0 + br0) * 1024 + k0 + bq0 * 4);
            b1N = *(const float4*)(Bm + (size_t)(n0 + br1) * 1024 + k0 + bq1 * 4);
        }
#pragma unroll
        for (int kk = 0; kk < 16; kk++) {
            unsigned long long rn2[4];
#pragma unroll
            for (int j = 0; j < 4; j++)
                rn2[j] = *(const unsigned long long*)&Bs[cur][kk][tx * 2 + 32 * j];
#pragma unroll
            for (int i = 0; i < 4; i++) {
                float a = As[cur][kk][ty + 16 * i];
                unsigned long long am = pack2(a, a);
#pragma unroll
                for (int j = 0; j < 4; j++)
                    acc2[i][j] = fma2(am, rn2[j], acc2[i][j]);
            }
        }
        if (it < 63) {
            const int nxt = cur ^ 1;
            As[nxt][aq * 4 + 0][ar] = avN.x; As[nxt][aq * 4 + 1][ar] = avN.y;
            As[nxt][aq * 4 + 2][ar] = avN.z; As[nxt][aq * 4 + 3][ar] = avN.w;
            Bs[nxt][bq0 * 4 + 0][br0] = b0N.x; Bs[nxt][bq0 * 4 + 1][br0] = b0N.y;
            Bs[nxt][bq0 * 4 + 2][br0] = b0N.z; Bs[nxt][bq0 * 4 + 3][br0] = b0N.w;
            Bs[nxt][bq1 * 4 + 0][br1] = b1N.x; Bs[nxt][bq1 * 4 + 1][br1] = b1N.y;
            Bs[nxt][bq1 * 4 + 2][br1] = b1N.z; Bs[nxt][bq1 * 4 + 3][br1] = b1N.w;
            __syncthreads();
        }
    }

    float2 b2[4];
#pragma unroll
    for (int j = 0; j < 4; j++)
        b2[j] = *(const float2*)(bias + n0 + tx * 2 + 32 * j);

#pragma unroll
    for (int i = 0; i < 4; i++) {
        int m = m0 + ty + 16 * i;
        int orow = remap ? ((m & 63) * TS + (m >> 6)) : m;
#pragma unroll
        for (int j = 0; j < 4; j++) {
            float2 v = unpack2(acc2[i][j]);
            float2 o = {v.x + b2[j].x, v.y + b2[j].y};
            *(float2*)(C + (size_t)orow * ldc + n0 + tx * 2 + 32 * j) = o;
        }
    }
}

// ---------------- persistent GRU recurrence v3: gate-local CTAs ----------------
// CTA owns 8 j-cols x 3 gates = 24 full-K W_hh rows in smem (96KB).
// K split over the 8 warps (128 k each); smem reduction; gates computed
// locally; ONE grid barrier per step.
__global__ __launch_bounds__(256, 1) void recurrent(
    const float* __restrict__ Whh, const float* __restrict__ bhh,
    const int* __restrict__ y, const float* __restrict__ h0)
{
    extern __shared__ float smem[];
    float* w_s = smem;                       // [1024 k][24 rows]
    int* y_si = (int*)(smem + Y_OFF);

    const int tid = threadIdx.x;
    const int lane = tid & 31;
    const int warp = tid >> 5;
    const int cta = blockIdx.x;
    const int rg = lane >> 3;                // 0..3 -> rows rg*6..+5
    const int bg = lane & 7;                 // 0..7 -> bpairs bg+8jj
    const int hb_b = tid >> 2, hb_fq = tid & 3;   // h loader mapping

    unsigned target = *(volatile unsigned*)&g_bar_phase;

    // ---- load W slice once: local row rho -> global row (rho/8)*1024 + cta*8 + rho%8
#pragma unroll 4
    for (int p = 0; p < 24; p++) {
        int e = p * 256 + tid;
        int rho = e >> 8;
        int f4 = e & 255;
        int grow = (rho >> 3) * 1024 + cta * 8 + (rho & 7);
        float4 wv = *(const float4*)(Whh + (size_t)grow * DD + f4 * 4);
        w_s[(f4 * 4 + 0) * 24 + rho] = wv.x;
        w_s[(f4 * 4 + 1) * 24 + rho] = wv.y;
        w_s[(f4 * 4 + 2) * 24 + rho] = wv.z;
        w_s[(f4 * 4 + 3) * 24 + rho] = wv.w;
    }

    // broadcast initial_state into h buffer 0
    for (int e = cta * 256 + tid; e < BB * DD; e += NCTA * 256)
        g_hbuf[0][e] = h0[e & (DD - 1)];
    gsync(++target);

#pragma unroll 1
    for (int t = 0; t < TS; t++) {
        const float* __restrict__ hc = g_hbuf[t & 1];
        float* __restrict__ hn = g_hbuf[(t + 1) & 1];

        // chunk 0 of h -> smem buf0 (transposed [k][b], stride 66)
        {
            float4 p0[8];
#pragma unroll
            for (int u = 0; u < 8; u++)
                p0[u] = __ldcg((const float4*)(hc + hb_b * DD + (hb_fq + 4 * u) * 4));
            float* hb = smem + H_OFF;
#pragma unroll
            for (int u = 0; u < 8; u++) {
                int kap = (hb_fq + 4 * u) * 4;
                hb[(kap + 0) * HB_STRIDE + hb_b] = p0[u].x;
                hb[(kap + 1) * HB_STRIDE + hb_b] = p0[u].y;
                hb[(kap + 2) * HB_STRIDE + hb_b] = p0[u].z;
                hb[(kap + 3) * HB_STRIDE + hb_b] = p0[u].w;
            }
        }
        if (tid < BB) y_si[tid] = (t == 0) ? 0 : y[tid * UU + t - 1];
        __syncthreads();

        // ---- mainloop: warp w covers k = c*128 + warp*16 + kap ----
        unsigned long long acc2[6][4];
#pragma unroll
        for (int i = 0; i < 6; i++)
#pragma unroll
            for (int jj = 0; jj < 4; jj++) acc2[i][jj] = 0ull;

#pragma unroll 1
        for (int c = 0; c < 8; c++) {
            float4 pf[8];
            if (c < 7) {
#pragma unroll
                for (int u = 0; u < 8; u++)
                    pf[u] = __ldcg((const float4*)(hc + hb_b * DD + (c + 1) * 128 + (hb_fq + 4 * u) * 4));
            }
            const float* hb = smem + H_OFF + (c & 1) * HB_FLOATS;
            const float* wb = w_s + c * 128 * 24;
#pragma unroll
            for (int kap = 0; kap < 16; kap++) {
                const int kk = warp * 16 + kap;
                unsigned long long rh2[4];
#pragma unroll
                for (int jj = 0; jj < 4; jj++)
                    rh2[jj] = *(const unsigned long long*)&hb[kk * HB_STRIDE + 2 * (bg + 8 * jj)];
#pragma unroll
                for (int i = 0; i < 6; i++) {
                    float wv = wb[kk * 24 + rg * 6 + i];
                    unsigned long long w2 = pack2(wv, wv);
#pragma unroll
                    for (int jj = 0; jj < 4; jj++)
                        acc2[i][jj] = fma2(rh2[jj], w2, acc2[i][jj]);
                }
            }
            if (c < 7) {
                float* hb2 = smem + H_OFF + ((c + 1) & 1) * HB_FLOATS;
#pragma unroll
                for (int u = 0; u < 8; u++) {
                    int kap = (hb_fq + 4 * u) * 4;
                    hb2[(kap + 0) * HB_STRIDE + hb_b] = pf[u].x;
                    hb2[(kap + 1) * HB_STRIDE + hb_b] = pf[u].y;
                    hb2[(kap + 2) * HB_STRIDE + hb_b] = pf[u].z;
                    hb2[(kap + 3) * HB_STRIDE + hb_b] = pf[u].w;
                }
                __syncthreads();
            }
        }
        __syncthreads();   // all h buffers consumed -> safe to overlay partials

        // ---- per-warp partials -> smem (overlay on h region), stride-33 ull ----
        unsigned long long* redq = (unsigned long long*)(smem + H_OFF);
#pragma unroll
        for (int i = 0; i < 6; i++)
#pragma unroll
            for (int jj = 0; jj < 4; jj++)
                redq[((size_t)warp * 24 + rg * 6 + i) * 33 + bg + 8 * jj] = acc2[i][jj];
        __syncthreads();

        // ---- reduce 8 warps + gates (thread: jl = tid&7, bpair bb = tid>>3) ----
        {
            const int jl = tid & 7;
            const int bb = tid >> 3;
            const int j = cta * 8 + jl;
            const float2* red2 = (const float2*)(smem + H_OFF);
            float2 sr = {0.f, 0.f}, sz = {0.f, 0.f}, sn = {0.f, 0.f};
#pragma unroll
            for (int w = 0; w < 8; w++) {
                float2 a = red2[(w * 24 + jl) * 33 + bb];
                float2 b = red2[(w * 24 + 8 + jl) * 33 + bb];
                float2 cpl = red2[(w * 24 + 16 + jl) * 33 + bb];
                sr.x += a.x; sr.y += a.y;
                sz.x += b.x; sz.y += b.y;
                sn.x += cpl.x; sn.y += cpl.y;
            }
            const float brr = bhh[j], bzz = bhh[DD + j], bnn = bhh[2 * DD + j];
            const int b0 = 2 * bb, b1 = 2 * bb + 1;
            const int tok0 = y_si[b0], tok1 = y_si[b1];
            const float* t0 = g_table + (size_t)tok0 * G3;
            const float* t1 = g_table + (size_t)tok1 * G3;
            float h00 = __ldcg(hc + (size_t)b0 * DD + j);
            float h01 = __ldcg(hc + (size_t)b1 * DD + j);
            float xr0 = t0[j] + sr.x + brr,      xr1 = t1[j] + sr.y + brr;
            float xz0 = t0[DD + j] + sz.x + bzz, xz1 = t1[DD + j] + sz.y + bzz;
            float gn0 = sn.x + bnn,              gn1 = sn.y + bnn;
            float xn0 = t0[2 * DD + j],          xn1 = t1[2 * DD + j];
            float r0 = 1.f / (1.f + __expf(-xr0)), r1 = 1.f / (1.f + __expf(-xr1));
            float z0 = 1.f / (1.f + __expf(-xz0)), z1 = 1.f / (1.f + __expf(-xz1));
            float n0 = tanhf(xn0 + r0 * gn0),      n1 = tanhf(xn1 + r1 * gn1);
            float hv0 = (1.f - z0) * n0 + z0 * h00;
            float hv1 = (1.f - z1) * n1 + z1 * h01;
            hn[(size_t)b0 * DD + j] = hv0;
            hn[(size_t)b1 * DD + j] = hv1;
            g_hs[((size_t)t * BB + b0) * DD + j] = hv0;
            g_hs[((size_t)t * BB + b1) * DD + j] = hv1;
        }
        gsync(++target);     // ONE grid barrier per step
    }
}

// ---------------- launch ----------------
extern "C" void kernel_launch(void* const* d_in, const int* in_sizes, int n_in,
                              void* d_out, int out_size) {
    const int*   y     = (const int*)d_in[0];
    const float* embed = (const float*)d_in[1];
    const float* wih   = (const float*)d_in[2];
    const float* bih   = (const float*)d_in[3];
    const float* whh   = (const float*)d_in[4];
    const float* bhh   = (const float*)d_in[5];
    const float* lw    = (const float*)d_in[6];
    const float* lb    = (const float*)d_in[7];
    const float* h0    = (const float*)d_in[8];
    float* out = (float*)d_out;

    float *tbl = nullptr, *hs = nullptr;
    cudaGetSymbolAddress((void**)&tbl, g_table);
    cudaGetSymbolAddress((void**)&hs, g_hs);

    const int rec_smem = SM_FLOATS * sizeof(float);   // ~166 KB
    static bool attr_done = false;
    if (!attr_done) {
        cudaFuncSetAttribute(recurrent, cudaFuncAttributeMaxDynamicSharedMemorySize, rec_smem);
        attr_done = true;
    }

    // 1) vocab table: table[v][0:3072] = embed[v]·W_ih^T + b_ih
    gemm_nt<<<dim3(G3 / 128, VV / 64), 256>>>(embed, wih, bih, tbl, G3, 0);
    // 2) persistent recurrence over 513 steps
    recurrent<<<NCTA, 256, rec_smem>>>(whh, bhh, y, h0);
    // 3) out[b][t][:] = hs[t*64+b]·linear_w^T + linear_b  (row remap in epilogue)
    gemm_nt<<<dim3(JJ / 128, (TS * BB) / 64), 256>>>(hs, lw, lb, out, JJ, 1);
}